// round 15
// baseline (speedup 1.0000x reference)
#include <cuda_runtime.h>
#include <cuda_bf16.h>

// out[e] = dot(src_feat[src_idx[e]], dst_feat[dst_idx[e]]), D=64 fp32.
//
// R5 (resubmission; prior attempts hit GPU-broker timeouts, never ran):
// persistent grid-stride kernel + index-prefetch software pipeline.
//  - 592 CTAs (~4/SM), each warp loops over edge tiles of 8 edges
//    (8-lane groups, 2 edges/thread -> 8 independent full-line LDG.128).
//  - Indices for the NEXT tile are loaded while the CURRENT tile's feature
//    loads are in flight, breaking the serial idx->feat dependency chain
//    (~600cyc -> ~300cyc exposed per tile).
//  - No wave transitions / CTA retire churn (R3/R4 had ~22 waves and
//    cross-CTA L1tex-queue spread).

__global__ void __launch_bounds__(256) sddmm_dot64_r5_kernel(
    const int* __restrict__ src_idx,
    const int* __restrict__ dst_idx,
    const float4* __restrict__ src_feat,   // [N, 16] float4
    const float4* __restrict__ dst_feat,   // [N, 16] float4
    float* __restrict__ out,
    int num_edges)
{
    const int tid   = blockIdx.x * blockDim.x + threadIdx.x;
    const int warp  = tid >> 5;
    const int w     = tid & 31;
    const int sg    = w >> 3;           // 8-lane sub-group: 0..3
    const int sl    = w & 7;            // lane in sub-group: 0..7
    const int nwarp = (gridDim.x * blockDim.x) >> 5;
    const int stride = nwarp * 8;       // edges consumed per iteration, all warps

    const int last = num_edges - 1;

    // First tile's edges for this thread.
    int eA = warp * 8 + sg;             // edge slot A
    // Prologue: load indices for the first tile (clamped; stores predicated).
    int s0 = __ldg(&src_idx[min(eA, last)]);
    int d0 = __ldg(&dst_idx[min(eA, last)]);
    int s1 = __ldg(&src_idx[min(eA + 4, last)]);
    int d1 = __ldg(&dst_idx[min(eA + 4, last)]);

    for (int e = eA; e < num_edges; e += stride) {
        // ---- issue 8 independent feature loads for the CURRENT tile ----
        const float4* ps0 = src_feat + (size_t)s0 * 16 + sl;
        const float4* pd0 = dst_feat + (size_t)d0 * 16 + sl;
        const float4* ps1 = src_feat + (size_t)s1 * 16 + sl;
        const float4* pd1 = dst_feat + (size_t)d1 * 16 + sl;

        float4 a0 = __ldg(ps0);
        float4 a1 = __ldg(ps0 + 8);
        float4 b0 = __ldg(pd0);
        float4 b1 = __ldg(pd0 + 8);
        float4 c0 = __ldg(ps1);
        float4 c1 = __ldg(ps1 + 8);
        float4 g0 = __ldg(pd1);
        float4 g1 = __ldg(pd1 + 8);

        // ---- prefetch NEXT tile's indices while features are in flight ----
        int en = e + stride;
        int enA = min(en, last);
        int enB = min(en + 4, last);
        int ns0 = __ldg(&src_idx[enA]);
        int nd0 = __ldg(&dst_idx[enA]);
        int ns1 = __ldg(&src_idx[enB]);
        int nd1 = __ldg(&dst_idx[enB]);

        // ---- compute current tile ----
        float pA = a0.x * b0.x + a0.y * b0.y + a0.z * b0.z + a0.w * b0.w
                 + a1.x * b1.x + a1.y * b1.y + a1.z * b1.z + a1.w * b1.w;
        float pB = c0.x * g0.x + c0.y * g0.y + c0.z * g0.z + c0.w * g0.w
                 + c1.x * g1.x + c1.y * g1.y + c1.z * g1.z + c1.w * g1.w;

        pA += __shfl_xor_sync(0xffffffffu, pA, 4);
        pB += __shfl_xor_sync(0xffffffffu, pB, 4);
        pA += __shfl_xor_sync(0xffffffffu, pA, 2);
        pB += __shfl_xor_sync(0xffffffffu, pB, 2);
        pA += __shfl_xor_sync(0xffffffffu, pA, 1);
        pB += __shfl_xor_sync(0xffffffffu, pB, 1);

        if (sl == 0) {
            out[e] = pA;                       // e < num_edges guaranteed
            if (e + 4 < num_edges) out[e + 4] = pB;
        }

        // rotate pipeline registers
        s0 = ns0; d0 = nd0; s1 = ns1; d1 = nd1;
    }
}

extern "C" void kernel_launch(void* const* d_in, const int* in_sizes, int n_in,
                              void* d_out, int out_size)
{
    const int*    src_idx  = (const int*)d_in[0];
    const int*    dst_idx  = (const int*)d_in[1];
    const float4* src_feat = (const float4*)d_in[2];
    const float4* dst_feat = (const float4*)d_in[3];
    float*        out      = (float*)d_out;

    int num_edges = in_sizes[0];          // E = 1,250,000

    // Persistent launch: ~4 CTAs per SM (148 SMs on B300, 152 on GB300;
    // grid-stride loop is correct for any count).
    int threads = 256;
    int blocks  = 592;

    sddmm_dot64_r5_kernel<<<blocks, threads>>>(src_idx, dst_idx,
                                               src_feat, dst_feat,
                                               out, num_edges);
}